// round 1
// baseline (speedup 1.0000x reference)
#include <cuda_runtime.h>

#define H 64
#define B 16
#define L 512
#define TOK_PER_BLOCK 8
#define TOKENS_PER_BATCH (2 * L)                      // 1024
#define CHUNKS_PER_BATCH (TOKENS_PER_BATCH / TOK_PER_BLOCK)  // 128
#define NBLOCKS (B * CHUNKS_PER_BATCH)                // 2048

// Scratch accumulator (allocation-free per harness rules)
__device__ float g_h[B * H];

__global__ void zero_kernel() {
    int i = blockIdx.x * blockDim.x + threadIdx.x;
    if (i < B * H) g_h[i] = 0.0f;
}

// Each block: one batch b, 8 tokens. 256 threads.
// Thread layout: hb = (t&15)*4 -> 4 consecutive h columns via float4;
//                wg = t>>4    -> row group, rows w = wg + 16*it, it=0..3.
// For a fixed row w, the 16 threads of a row-group read 64 consecutive
// floats (256B) as float4 -> fully coalesced.
__global__ void __launch_bounds__(256, 8) accum_kernel(
    const int* __restrict__ s1, const int* __restrict__ s2,
    const float* __restrict__ embed, const float* __restrict__ sos_g)
{
    __shared__ float s_sos[H];
    __shared__ float s_red[H];
    const int t = threadIdx.x;
    if (t < H) { s_sos[t] = sos_g[t]; s_red[t] = 0.0f; }
    __syncthreads();

    const int blk   = blockIdx.x;
    const int b     = blk / CHUNKS_PER_BATCH;
    const int chunk = blk % CHUNKS_PER_BATCH;
    const int tok0  = chunk * TOK_PER_BLOCK;   // in [0, 1024)

    const int hb = (t & 15) * 4;   // h base (0,4,...,60)
    const int wg = t >> 4;         // row group 0..15

    float acc0 = 0.f, acc1 = 0.f, acc2 = 0.f, acc3 = 0.f;

    #pragma unroll 1
    for (int k = 0; k < TOK_PER_BLOCK; ++k) {
        const int ti  = tok0 + k;
        const int tok = (ti < L) ? s1[b * L + ti] : s2[b * L + (ti - L)];
        const float4* Ep = (const float4*)(embed + (size_t)tok * (H * H));
        #pragma unroll
        for (int it = 0; it < 4; ++it) {
            const int w = wg + 16 * it;
            float4 v = __ldg(&Ep[w * 16 + (hb >> 2)]);
            const float sw = s_sos[w];
            acc0 = fmaf(sw, v.x, acc0);
            acc1 = fmaf(sw, v.y, acc1);
            acc2 = fmaf(sw, v.z, acc2);
            acc3 = fmaf(sw, v.w, acc3);
        }
    }

    // Block-level reduction over the 16 row-groups sharing each h.
    atomicAdd(&s_red[hb + 0], acc0);
    atomicAdd(&s_red[hb + 1], acc1);
    atomicAdd(&s_red[hb + 2], acc2);
    atomicAdd(&s_red[hb + 3], acc3);
    __syncthreads();

    if (t < H) atomicAdd(&g_h[b * H + t], s_red[t]);
}

// One block, warp b handles batch b.
// x[j] = relu(sum_k h[k]*w1[j,k] + b1[j]);  out[o] = sum_j x[j]*w2[o,j] + b2[o]
__global__ void __launch_bounds__(B * 32) mlp_kernel(
    const float* __restrict__ w1, const float* __restrict__ b1,
    const float* __restrict__ w2, const float* __restrict__ b2,
    float* __restrict__ out)
{
    const int warp = threadIdx.x >> 5;
    const int lane = threadIdx.x & 31;
    const float* h = g_h + warp * H;

    float x0 = b1[lane];
    float x1 = b1[lane + 32];
    #pragma unroll
    for (int k = 0; k < H; ++k) {
        const float hk = h[k];
        x0 = fmaf(hk, w1[lane * H + k],        x0);
        x1 = fmaf(hk, w1[(lane + 32) * H + k], x1);
    }
    x0 = fmaxf(x0, 0.0f);
    x1 = fmaxf(x1, 0.0f);

    float o0 = x0 * w2[lane]     + x1 * w2[lane + 32];
    float o1 = x0 * w2[H + lane] + x1 * w2[H + lane + 32];
    #pragma unroll
    for (int off = 16; off > 0; off >>= 1) {
        o0 += __shfl_xor_sync(0xffffffffu, o0, off);
        o1 += __shfl_xor_sync(0xffffffffu, o1, off);
    }
    if (lane == 0) {
        out[warp * 2 + 0] = o0 + b2[0];
        out[warp * 2 + 1] = o1 + b2[1];
    }
}

extern "C" void kernel_launch(void* const* d_in, const int* in_sizes, int n_in,
                              void* d_out, int out_size) {
    const int*   s1    = (const int*)  d_in[0];
    const int*   s2    = (const int*)  d_in[1];
    const float* embed = (const float*)d_in[2];
    const float* sos   = (const float*)d_in[3];
    const float* w1    = (const float*)d_in[4];
    const float* b1    = (const float*)d_in[5];
    const float* w2    = (const float*)d_in[6];
    const float* b2    = (const float*)d_in[7];
    float* out = (float*)d_out;

    zero_kernel<<<1, B * H>>>();
    accum_kernel<<<NBLOCKS, 256>>>(s1, s2, embed, sos);
    mlp_kernel<<<1, B * 32>>>(w1, b1, w2, b2, out);
}

// round 6
// speedup vs baseline: 2.1431x; 2.1431x over previous
#include <cuda_runtime.h>

#define H 64
#define B 16
#define L 512
#define TOK_PER_BLOCK 8
#define TOKENS_PER_BATCH (2 * L)                              // 1024
#define CHUNKS_PER_BATCH (TOKENS_PER_BATCH / TOK_PER_BLOCK)   // 128
#define NBLOCKS (B * CHUNKS_PER_BATCH)                        // 2048

// Per-block partial sums (plain stores; no zeroing, no atomics needed)
__device__ float g_part[NBLOCKS * H];

// ---------------------------------------------------------------------------
// accum_kernel: one block = one batch b, 8 tokens. 256 threads.
// Thread layout: c4 = t & 15  -> float4 column index (h = c4*4 .. c4*4+3)
//                wg = t >> 4  -> row group; rows w = wg + 16*it, it=0..3
// For fixed w, the 16 threads of a row-group read 64 consecutive floats
// (256B) -> fully coalesced LDG.128.
// Token indices are preloaded into shared so the mainloop has NO dependent
// scalar loads; tokens are processed 2 at a time so 8 LDG.128 are in flight
// per thread (MLP_p1 = 8).
// ---------------------------------------------------------------------------
__global__ void __launch_bounds__(256, 4) accum_kernel(
    const int* __restrict__ s1, const int* __restrict__ s2,
    const float* __restrict__ embed, const float* __restrict__ sos_g)
{
    __shared__ float s_sos[H];
    __shared__ float s_red[H];
    __shared__ int   s_tok[TOK_PER_BLOCK];

    const int t = threadIdx.x;
    const int blk   = blockIdx.x;
    const int b     = blk / CHUNKS_PER_BATCH;
    const int chunk = blk % CHUNKS_PER_BATCH;
    const int tok0  = chunk * TOK_PER_BLOCK;       // in [0, 1024)

    if (t < H) { s_sos[t] = sos_g[t]; s_red[t] = 0.0f; }
    if (t < TOK_PER_BLOCK) {
        const int ti = tok0 + t;
        s_tok[t] = (ti < L) ? s1[b * L + ti] : s2[b * L + (ti - L)];
    }
    __syncthreads();

    const int c4 = t & 15;    // float4 column index
    const int wg = t >> 4;    // row group 0..15

    float acc0 = 0.f, acc1 = 0.f, acc2 = 0.f, acc3 = 0.f;

    #pragma unroll
    for (int k = 0; k < TOK_PER_BLOCK; k += 2) {
        const float4* E0 = (const float4*)(embed) + (size_t)s_tok[k]     * (H * H / 4);
        const float4* E1 = (const float4*)(embed) + (size_t)s_tok[k + 1] * (H * H / 4);

        float4 v0[4], v1[4];
        #pragma unroll
        for (int it = 0; it < 4; ++it) {
            const int w = wg + 16 * it;
            v0[it] = __ldg(&E0[w * 16 + c4]);
        }
        #pragma unroll
        for (int it = 0; it < 4; ++it) {
            const int w = wg + 16 * it;
            v1[it] = __ldg(&E1[w * 16 + c4]);
        }
        #pragma unroll
        for (int it = 0; it < 4; ++it) {
            const float sw = s_sos[wg + 16 * it];
            acc0 = fmaf(sw, v0[it].x, acc0);
            acc1 = fmaf(sw, v0[it].y, acc1);
            acc2 = fmaf(sw, v0[it].z, acc2);
            acc3 = fmaf(sw, v0[it].w, acc3);
        }
        #pragma unroll
        for (int it = 0; it < 4; ++it) {
            const float sw = s_sos[wg + 16 * it];
            acc0 = fmaf(sw, v1[it].x, acc0);
            acc1 = fmaf(sw, v1[it].y, acc1);
            acc2 = fmaf(sw, v1[it].z, acc2);
            acc3 = fmaf(sw, v1[it].w, acc3);
        }
    }

    // Fold lanes l and l+16 (same c4, adjacent row-groups) inside each warp.
    acc0 += __shfl_xor_sync(0xffffffffu, acc0, 16);
    acc1 += __shfl_xor_sync(0xffffffffu, acc1, 16);
    acc2 += __shfl_xor_sync(0xffffffffu, acc2, 16);
    acc3 += __shfl_xor_sync(0xffffffffu, acc3, 16);

    // Remaining 8 row-group partials per h -> shared atomics (spread addrs).
    if ((t & 31) < 16) {
        const int hb = c4 * 4;
        atomicAdd(&s_red[hb + 0], acc0);
        atomicAdd(&s_red[hb + 1], acc1);
        atomicAdd(&s_red[hb + 2], acc2);
        atomicAdd(&s_red[hb + 3], acc3);
    }
    __syncthreads();

    if (t < H) g_part[blk * H + t] = s_red[t];
}

// ---------------------------------------------------------------------------
// mlp_kernel: one block per batch (16 blocks, 128 threads).
// Phase 1: reduce the 128 chunk-partials for this batch -> s_h[64].
// Phase 2: warp 0 computes Linear(64->64)+ReLU+Linear(64->2).
// ---------------------------------------------------------------------------
__global__ void __launch_bounds__(128) mlp_kernel(
    const float* __restrict__ w1, const float* __restrict__ b1,
    const float* __restrict__ w2, const float* __restrict__ b2,
    float* __restrict__ out)
{
    __shared__ float s_part[128];
    __shared__ float s_h[H];

    const int b = blockIdx.x;
    const int t = threadIdx.x;
    const int h    = t & 63;
    const int half = t >> 6;   // 0 or 1

    float sum = 0.0f;
    const float* base = g_part + (size_t)(b * CHUNKS_PER_BATCH) * H + h;
    #pragma unroll 8
    for (int c = 0; c < CHUNKS_PER_BATCH / 2; ++c)
        sum += base[(half * (CHUNKS_PER_BATCH / 2) + c) * H];
    s_part[t] = sum;
    __syncthreads();
    if (t < H) s_h[t] = s_part[t] + s_part[t + H];
    __syncthreads();

    if (t < 32) {
        const int lane = t;
        float x0 = b1[lane];
        float x1 = b1[lane + 32];
        #pragma unroll
        for (int k = 0; k < H; ++k) {
            const float hk = s_h[k];
            x0 = fmaf(hk, w1[lane * H + k],        x0);
            x1 = fmaf(hk, w1[(lane + 32) * H + k], x1);
        }
        x0 = fmaxf(x0, 0.0f);
        x1 = fmaxf(x1, 0.0f);

        float o0 = x0 * w2[lane]     + x1 * w2[lane + 32];
        float o1 = x0 * w2[H + lane] + x1 * w2[H + lane + 32];
        #pragma unroll
        for (int off = 16; off > 0; off >>= 1) {
            o0 += __shfl_xor_sync(0xffffffffu, o0, off);
            o1 += __shfl_xor_sync(0xffffffffu, o1, off);
        }
        if (lane == 0) {
            out[b * 2 + 0] = o0 + b2[0];
            out[b * 2 + 1] = o1 + b2[1];
        }
    }
}

extern "C" void kernel_launch(void* const* d_in, const int* in_sizes, int n_in,
                              void* d_out, int out_size) {
    const int*   s1    = (const int*)  d_in[0];
    const int*   s2    = (const int*)  d_in[1];
    const float* embed = (const float*)d_in[2];
    const float* sos   = (const float*)d_in[3];
    const float* w1    = (const float*)d_in[4];
    const float* b1    = (const float*)d_in[5];
    const float* w2    = (const float*)d_in[6];
    const float* b2    = (const float*)d_in[7];
    float* out = (float*)d_out;

    accum_kernel<<<NBLOCKS, 256>>>(s1, s2, embed, sos);
    mlp_kernel<<<B, 128>>>(w1, b1, w2, b2, out);
}